// round 1
// baseline (speedup 1.0000x reference)
#include <cuda_runtime.h>

// Problem constants: B=2, T=2048, C=1024, H=16, D=64, causal MHA, fp32.
#define BB 2
#define TT 2048
#define CC 1024
#define HH 16
#define DD 64

// Scratch (allocation-free): Q,K,V in [B,H,T,D], attended in [B,T,C].
__device__ float g_q[BB*HH*TT*DD];
__device__ float g_k[BB*HH*TT*DD];
__device__ float g_v[BB*HH*TT*DD];
__device__ float g_att[BB*TT*CC];

// ---------------------------------------------------------------------------
// Projection GEMM: out = A[M,K] @ W[K,N] + bias, M=4096, N=K=1024.
// Tile 64x64x16, 256 threads, 4x4 per thread.
// REMAP=true writes into [B,H,T,D] layout (row m=b*T+t, col n=h*D+d).
// ---------------------------------------------------------------------------
template<bool REMAP>
__global__ __launch_bounds__(256) void proj_kernel(
    const float* __restrict__ A, const float* __restrict__ W,
    const float* __restrict__ bias, float* __restrict__ out)
{
    const int Ndim = 1024, Kdim = 1024;
    __shared__ float As[16*65];   // As[k][m], stride 65 (scalar reads, broadcast)
    __shared__ float Bs[16*68];   // Bs[k][n], stride 68 (16B-aligned float4)

    int tid = threadIdx.x;
    int tx = tid & 15, ty = tid >> 4;
    int bn = blockIdx.x * 64, bm = blockIdx.y * 64;

    float acc[4][4] = {};

    int arow = tid >> 2,  ac4 = (tid & 3)  << 2;   // A tile: 64 rows x 16 cols
    int brow = tid >> 4,  bc4 = (tid & 15) << 2;   // W tile: 16 rows x 64 cols

    for (int k0 = 0; k0 < Kdim; k0 += 16) {
        float4 a = *(const float4*)(A + (size_t)(bm + arow)*Kdim + k0 + ac4);
        As[(ac4+0)*65 + arow] = a.x;
        As[(ac4+1)*65 + arow] = a.y;
        As[(ac4+2)*65 + arow] = a.z;
        As[(ac4+3)*65 + arow] = a.w;
        *(float4*)(Bs + brow*68 + bc4) =
            *(const float4*)(W + (size_t)(k0 + brow)*Ndim + bn + bc4);
        __syncthreads();
#pragma unroll
        for (int kk = 0; kk < 16; kk++) {
            float av[4];
#pragma unroll
            for (int i = 0; i < 4; i++) av[i] = As[kk*65 + ty + 16*i];
            float4 bv = *(float4*)(Bs + kk*68 + 4*tx);
#pragma unroll
            for (int i = 0; i < 4; i++) {
                acc[i][0] += av[i]*bv.x;
                acc[i][1] += av[i]*bv.y;
                acc[i][2] += av[i]*bv.z;
                acc[i][3] += av[i]*bv.w;
            }
        }
        __syncthreads();
    }

    float4 bb = *(const float4*)(bias + bn + 4*tx);
#pragma unroll
    for (int i = 0; i < 4; i++) {
        int m = bm + ty + 16*i;
        float4 r = make_float4(acc[i][0]+bb.x, acc[i][1]+bb.y,
                               acc[i][2]+bb.z, acc[i][3]+bb.w);
        if (REMAP) {
            int b = m >> 11, t = m & (TT-1);
            int h = bn >> 6;                 // BN==D==64: one head per block col
            *(float4*)(out + ((size_t)((b*HH + h)*TT + t))*DD + 4*tx) = r;
        } else {
            *(float4*)(out + (size_t)m*Ndim + bn + 4*tx) = r;
        }
    }
}

// ---------------------------------------------------------------------------
// Causal flash attention, fp32. One block = (bh, 64-query tile).
// 256 threads; thread owns queries {ty+16i}, output dims {4tx+j}.
// smem strides 68 -> 16B-aligned float4, <=2-way conflicts.
// ---------------------------------------------------------------------------
__global__ __launch_bounds__(256) void attn_kernel()
{
    extern __shared__ float sm[];
    float* sQ  = sm;              // [64][68] row-major (scaled by 1/sqrt(D))
    float* sK  = sQ  + 64*68;     // [64][68]
    float* sV  = sK  + 64*68;     // [64][68]
    float* sS  = sV  + 64*68;     // [64][68] scores -> probabilities
    float* sMx = sS  + 64*68;     // [64] running max
    float* sL  = sMx + 64;        // [64] running sum
    float* sC  = sL  + 64;        // [64] correction factor

    int tid = threadIdx.x;
    int tx = tid & 15, ty = tid >> 4;
    int bh = blockIdx.y;
    int qi = (int)gridDim.x - 1 - (int)blockIdx.x;   // heavy q-tiles first
    int q0 = qi * 64;

    const float* Qg = g_q + (size_t)bh*TT*DD;
    const float* Kg = g_k + (size_t)bh*TT*DD;
    const float* Vg = g_v + (size_t)bh*TT*DD;

    // Load + scale Q tile
#pragma unroll
    for (int it = 0; it < 4; it++) {
        int idx = it*256 + tid;
        int r = idx >> 4, c = (idx & 15) << 2;
        float4 v = *(const float4*)(Qg + (size_t)(q0 + r)*DD + c);
        v.x *= 0.125f; v.y *= 0.125f; v.z *= 0.125f; v.w *= 0.125f;
        *(float4*)(sQ + r*68 + c) = v;
    }
    if (tid < 64) { sMx[tid] = -1e30f; sL[tid] = 0.f; }

    float acc[4][4] = {};

    for (int kt = 0; kt <= qi; kt++) {
        __syncthreads();          // protect prior-iter smem reads (and Q load)
        int k0 = kt * 64;
#pragma unroll
        for (int it = 0; it < 4; it++) {
            int idx = it*256 + tid;
            int r = idx >> 4, c = (idx & 15) << 2;
            *(float4*)(sK + r*68 + c) = *(const float4*)(Kg + (size_t)(k0 + r)*DD + c);
            *(float4*)(sV + r*68 + c) = *(const float4*)(Vg + (size_t)(k0 + r)*DD + c);
        }
        __syncthreads();

        // S = Q K^T  (thread: rows ty+16i, key cols tx+16j)
        float s[4][4] = {};
#pragma unroll
        for (int d4 = 0; d4 < 64; d4 += 4) {
            float4 qv[4], kv[4];
#pragma unroll
            for (int i = 0; i < 4; i++) qv[i] = *(float4*)(sQ + (ty+16*i)*68 + d4);
#pragma unroll
            for (int j = 0; j < 4; j++) kv[j] = *(float4*)(sK + (tx+16*j)*68 + d4);
#pragma unroll
            for (int i = 0; i < 4; i++)
#pragma unroll
                for (int j = 0; j < 4; j++)
                    s[i][j] += qv[i].x*kv[j].x + qv[i].y*kv[j].y
                             + qv[i].z*kv[j].z + qv[i].w*kv[j].w;
        }
        bool diag = (kt == qi);
#pragma unroll
        for (int i = 0; i < 4; i++) {
            int q = ty + 16*i;
#pragma unroll
            for (int j = 0; j < 4; j++) {
                int c = tx + 16*j;
                float v = s[i][j];
                if (diag && c > q) v = -1e30f;   // causal mask (finite: no NaN)
                sS[q*68 + c] = v;
            }
        }
        __syncthreads();

        // Online softmax, one thread per query row
        if (tid < 64) {
            int q = tid;
            float mo = sMx[q];
            float mn = mo;
            for (int c = 0; c < 64; c++) mn = fmaxf(mn, sS[q*68 + c]);
            float corr = __expf(mo - mn);
            float l = sL[q] * corr;
            for (int c = 0; c < 64; c++) {
                float p = __expf(sS[q*68 + c] - mn);
                sS[q*68 + c] = p;
                l += p;
            }
            sMx[q] = mn; sL[q] = l; sC[q] = corr;
        }
        __syncthreads();

        // O = O*corr + P V  (thread: rows ty+16i, output dims 4tx+j)
#pragma unroll
        for (int i = 0; i < 4; i++) {
            float c_ = sC[ty + 16*i];
#pragma unroll
            for (int j = 0; j < 4; j++) acc[i][j] *= c_;
        }
#pragma unroll
        for (int k4 = 0; k4 < 64; k4 += 4) {
            float4 p[4], vv[4];
#pragma unroll
            for (int i = 0; i < 4; i++) p[i] = *(float4*)(sS + (ty+16*i)*68 + k4);
#pragma unroll
            for (int kk = 0; kk < 4; kk++) vv[kk] = *(float4*)(sV + (k4+kk)*68 + 4*tx);
#pragma unroll
            for (int i = 0; i < 4; i++) {
                acc[i][0] += p[i].x*vv[0].x + p[i].y*vv[1].x + p[i].z*vv[2].x + p[i].w*vv[3].x;
                acc[i][1] += p[i].x*vv[0].y + p[i].y*vv[1].y + p[i].z*vv[2].y + p[i].w*vv[3].y;
                acc[i][2] += p[i].x*vv[0].z + p[i].y*vv[1].z + p[i].z*vv[2].z + p[i].w*vv[3].z;
                acc[i][3] += p[i].x*vv[0].w + p[i].y*vv[1].w + p[i].z*vv[2].w + p[i].w*vv[3].w;
            }
        }
    }

    // Epilogue: normalize, write [B,T,C]
    int b = bh >> 4, h = bh & 15;
#pragma unroll
    for (int i = 0; i < 4; i++) {
        int q = ty + 16*i;
        float inv = 1.0f / sL[q];
        float4 r = make_float4(acc[i][0]*inv, acc[i][1]*inv,
                               acc[i][2]*inv, acc[i][3]*inv);
        *(float4*)(g_att + ((size_t)(b*TT + q0 + q))*CC + h*DD + 4*tx) = r;
    }
}

// ---------------------------------------------------------------------------
extern "C" void kernel_launch(void* const* d_in, const int* in_sizes, int n_in,
                              void* d_out, int out_size)
{
    (void)in_sizes; (void)n_in; (void)out_size;
    const float* x  = (const float*)d_in[0];
    const float* Wq = (const float*)d_in[1];
    const float* bq = (const float*)d_in[2];
    const float* Wk = (const float*)d_in[3];
    const float* bk = (const float*)d_in[4];
    const float* Wv = (const float*)d_in[5];
    const float* bv = (const float*)d_in[6];
    const float* Wo = (const float*)d_in[7];
    const float* bo = (const float*)d_in[8];
    float* out = (float*)d_out;

    float *q, *k, *v, *att;
    cudaGetSymbolAddress((void**)&q,   g_q);
    cudaGetSymbolAddress((void**)&k,   g_k);
    cudaGetSymbolAddress((void**)&v,   g_v);
    cudaGetSymbolAddress((void**)&att, g_att);

    dim3 pgrid(CC/64, (BB*TT)/64);   // (16, 64)
    proj_kernel<true><<<pgrid, 256>>>(x, Wq, bq, q);
    proj_kernel<true><<<pgrid, 256>>>(x, Wk, bk, k);
    proj_kernel<true><<<pgrid, 256>>>(x, Wv, bv, v);

    const int attn_smem = (4*64*68 + 3*64) * (int)sizeof(float);  // 70400 B
    cudaFuncSetAttribute(attn_kernel,
                         cudaFuncAttributeMaxDynamicSharedMemorySize, attn_smem);
    attn_kernel<<<dim3(TT/64, BB*HH), 256, attn_smem>>>();

    proj_kernel<false><<<pgrid, 256>>>(att, Wo, bo, out);
}

// round 3
// speedup vs baseline: 2.0251x; 2.0251x over previous
#include <cuda_runtime.h>
#include <cuda_bf16.h>
#include <cstdint>

// B=2, T=2048, C=1024, H=16, D=64, causal MHA, fp32 in/out.
#define BB 2
#define TT 2048
#define CC 1024
#define HH 16
#define DD 64
#define MM (BB*TT)

typedef __nv_bfloat16 bf16;

// ---------------- scratch (allocation-free) ----------------
__device__ float g_q[BB*HH*TT*DD];
__device__ float g_k[BB*HH*TT*DD];
__device__ float g_v[BB*HH*TT*DD];
__device__ bf16  g_xh[MM*CC], g_xl[MM*CC];       // split of x
__device__ bf16  g_ah[MM*CC], g_al[MM*CC];       // split of attended
__device__ bf16  g_wh[4*CC*CC], g_wl[4*CC*CC];   // transposed weight splits [n][k]

// ---------------- helpers (portable PTX only: sm_80 baseline) ----------------
__device__ __forceinline__ uint32_t smem_u32(const void* p) {
    return (uint32_t)__cvta_generic_to_shared(p);
}

#define CP16(dst, src) \
    asm volatile("cp.async.cg.shared.global [%0], [%1], 16;" :: "r"(dst), "l"(src) : "memory")

__device__ __forceinline__ void ldm4(uint32_t* r, uint32_t a) {
    asm volatile("ldmatrix.sync.aligned.m8n8.x4.shared.b16 {%0,%1,%2,%3}, [%4];"
                 : "=r"(r[0]), "=r"(r[1]), "=r"(r[2]), "=r"(r[3]) : "r"(a));
}

__device__ __forceinline__ void mma_bf16(float* d, const uint32_t* a, const uint32_t* b) {
    asm volatile("mma.sync.aligned.m16n8k16.row.col.f32.bf16.bf16.f32 "
                 "{%0,%1,%2,%3}, {%4,%5,%6,%7}, {%8,%9}, {%0,%1,%2,%3};"
                 : "+f"(d[0]), "+f"(d[1]), "+f"(d[2]), "+f"(d[3])
                 : "r"(a[0]), "r"(a[1]), "r"(a[2]), "r"(a[3]), "r"(b[0]), "r"(b[1]));
}

// ---------------------------------------------------------------------------
// split x -> (hi, lo) bf16
// ---------------------------------------------------------------------------
__global__ void split_kernel(const float* __restrict__ x,
                             bf16* __restrict__ hi, bf16* __restrict__ lo) {
    int i = blockIdx.x * blockDim.x + threadIdx.x;
    float4 v = ((const float4*)x)[i];
    bf16 h0 = __float2bfloat16(v.x), h1 = __float2bfloat16(v.y);
    bf16 h2 = __float2bfloat16(v.z), h3 = __float2bfloat16(v.w);
    bf16 l0 = __float2bfloat16(v.x - __bfloat162float(h0));
    bf16 l1 = __float2bfloat16(v.y - __bfloat162float(h1));
    bf16 l2 = __float2bfloat16(v.z - __bfloat162float(h2));
    bf16 l3 = __float2bfloat16(v.w - __bfloat162float(h3));
    __nv_bfloat162* hp = (__nv_bfloat162*)(hi + 4*(size_t)i);
    __nv_bfloat162* lp = (__nv_bfloat162*)(lo + 4*(size_t)i);
    hp[0] = __nv_bfloat162(h0, h1); hp[1] = __nv_bfloat162(h2, h3);
    lp[0] = __nv_bfloat162(l0, l1); lp[1] = __nv_bfloat162(l2, l3);
}

// ---------------------------------------------------------------------------
// transpose + split: W[k][n] fp32 -> Wt_hi/lo[n][k] bf16
// ---------------------------------------------------------------------------
__global__ void tsplit_kernel(const float* __restrict__ W,
                              bf16* __restrict__ hi, bf16* __restrict__ lo) {
    __shared__ float t[32][33];
    int tx = threadIdx.x, ty = threadIdx.y;          // (32, 8)
    int n0 = blockIdx.x * 32, k0 = blockIdx.y * 32;
#pragma unroll
    for (int i = 0; i < 4; i++)
        t[ty + 8*i][tx] = W[(size_t)(k0 + ty + 8*i) * CC + n0 + tx];
    __syncthreads();
#pragma unroll
    for (int i = 0; i < 4; i++) {
        float v = t[tx][ty + 8*i];
        bf16 h = __float2bfloat16(v);
        bf16 l = __float2bfloat16(v - __bfloat162float(h));
        size_t o = (size_t)(n0 + ty + 8*i) * CC + k0 + tx;
        hi[o] = h; lo[o] = l;
    }
}

// ---------------------------------------------------------------------------
// mma.sync bf16x3 GEMM: out[M,N] = A @ Wt^T + bias.
// 128x128x64 tiles, cp.async 2-stage, XOR-swizzled smem, 8 warps (64x32 each).
// MODE 0: remap to [B,H,T,D].  MODE 1: plain [M,N].
// Smem stage: Ah | Al | Bh | Bl, each [128 rows][64 k] bf16 = 16KB. Stage=64KB.
// phys(row, ck16B) = row*128 + ((ck ^ (row&7)) << 4)  -> conflict-free ldmatrix.
// ---------------------------------------------------------------------------
template<int MODE>
__global__ __launch_bounds__(256) void gemm_bf16x3(
    const bf16* __restrict__ Ah, const bf16* __restrict__ Al,
    const bf16* __restrict__ Bh, const bf16* __restrict__ Bl,
    const float* __restrict__ bias, float* __restrict__ out)
{
    extern __shared__ char smraw[];
    const uint32_t sbase = smem_u32(smraw);

    int tid = threadIdx.x, lane = tid & 31, wid = tid >> 5;
    int wm = wid & 1, wn = wid >> 1;                 // 2 x 4 warp grid
    int m0 = blockIdx.y << 7, n0 = blockIdx.x << 7;

    float acc[4][4][4] = {};

    // ldmatrix per-lane geometry
    int arow = wm*64 + (lane & 15);
    int ahalf = lane >> 4;                            // k 16B-chunk half
    int brow = wn*32 + ((lane >> 4) << 3) + (lane & 7);
    int bhalf = (lane >> 3) & 1;

    // stage loader: 4 x 16B per thread per matrix
    auto load_stage = [&](int kt, int s) {
        uint32_t sb = sbase + s * 65536;
#pragma unroll
        for (int i = 0; i < 4; i++) {
            int id = tid + i*256;
            int r = id >> 3, c = id & 7;
            uint32_t phys = (uint32_t)(r*128 + ((c ^ (r & 7)) << 4));
            size_t ga = (size_t)(m0 + r)*CC + kt*64 + c*8;
            size_t gb = (size_t)(n0 + r)*CC + kt*64 + c*8;
            CP16(sb +         phys, Ah + ga);
            CP16(sb + 16384 + phys, Al + ga);
            CP16(sb + 32768 + phys, Bh + gb);
            CP16(sb + 49152 + phys, Bl + gb);
        }
        asm volatile("cp.async.commit_group;" ::: "memory");
    };

    load_stage(0, 0);

    for (int kt = 0; kt < 16; kt++) {
        if (kt + 1 < 16) {
            load_stage(kt + 1, (kt + 1) & 1);
            asm volatile("cp.async.wait_group 1;" ::: "memory");
        } else {
            asm volatile("cp.async.wait_group 0;" ::: "memory");
        }
        __syncthreads();

        uint32_t sb = sbase + (kt & 1) * 65536;
#pragma unroll
        for (int kk = 0; kk < 4; kk++) {
            uint32_t aswz = (uint32_t)(((kk*2 + ahalf) ^ (arow & 7)) << 4);
            uint32_t bswz = (uint32_t)(((kk*2 + bhalf) ^ (brow & 7)) << 4);
            uint32_t ahr[4][4], alr[4][4], bhr[2][4], blr[2][4];
#pragma unroll
            for (int mf = 0; mf < 4; mf++) {
                uint32_t off = (uint32_t)((arow + mf*16) * 128) + aswz;
                ldm4(ahr[mf], sb + off);
                ldm4(alr[mf], sb + 16384 + off);
            }
#pragma unroll
            for (int nh = 0; nh < 2; nh++) {
                uint32_t off = (uint32_t)((brow + nh*16) * 128) + bswz;
                ldm4(bhr[nh], sb + 32768 + off);
                ldm4(blr[nh], sb + 49152 + off);
            }
#pragma unroll
            for (int mf = 0; mf < 4; mf++)
#pragma unroll
                for (int nf = 0; nf < 4; nf++) {
                    const uint32_t* ph = bhr[nf >> 1] + (nf & 1)*2;
                    const uint32_t* pl = blr[nf >> 1] + (nf & 1)*2;
                    mma_bf16(acc[mf][nf], ahr[mf], ph);   // Ah*Bh
                    mma_bf16(acc[mf][nf], ahr[mf], pl);   // Ah*Bl
                    mma_bf16(acc[mf][nf], alr[mf], ph);   // Al*Bh
                }
        }
        __syncthreads();
    }

    // epilogue
    int g = lane >> 2, t2 = (lane & 3) * 2;
#pragma unroll
    for (int nf = 0; nf < 4; nf++) {
        int col = n0 + wn*32 + nf*8 + t2;
        float2 bb = *(const float2*)(bias + col);
#pragma unroll
        for (int mf = 0; mf < 4; mf++) {
            int m1 = m0 + wm*64 + mf*16 + g;
            float2 v1 = make_float2(acc[mf][nf][0] + bb.x, acc[mf][nf][1] + bb.y);
            float2 v2 = make_float2(acc[mf][nf][2] + bb.x, acc[mf][nf][3] + bb.y);
            if (MODE == 0) {
                int h = col >> 6, d = col & 63;
                int b1 = m1 >> 11, t1 = m1 & (TT - 1);
                float* base = out + ((size_t)(b1*HH + h)*TT) * DD + d;
                *(float2*)(base + (size_t)t1 * DD)       = v1;
                *(float2*)(base + (size_t)(t1 + 8) * DD) = v2;
            } else {
                *(float2*)(out + (size_t)m1*CC + col)       = v1;
                *(float2*)(out + (size_t)(m1 + 8)*CC + col) = v2;
            }
        }
    }
}

// ---------------------------------------------------------------------------
// Causal flash attention, fp32; epilogue writes split bf16 attended [B,T,C].
// ---------------------------------------------------------------------------
__global__ __launch_bounds__(256) void attn_kernel()
{
    extern __shared__ float sm[];
    float* sQ  = sm;
    float* sK  = sQ  + 64*68;
    float* sV  = sK  + 64*68;
    float* sS  = sV  + 64*68;
    float* sMx = sS  + 64*68;
    float* sL  = sMx + 64;
    float* sC  = sL  + 64;

    int tid = threadIdx.x;
    int tx = tid & 15, ty = tid >> 4;
    int bh = blockIdx.y;
    int qi = (int)gridDim.x - 1 - (int)blockIdx.x;
    int q0 = qi * 64;

    const float* Qg = g_q + (size_t)bh*TT*DD;
    const float* Kg = g_k + (size_t)bh*TT*DD;
    const float* Vg = g_v + (size_t)bh*TT*DD;

#pragma unroll
    for (int it = 0; it < 4; it++) {
        int idx = it*256 + tid;
        int r = idx >> 4, c = (idx & 15) << 2;
        float4 v = *(const float4*)(Qg + (size_t)(q0 + r)*DD + c);
        v.x *= 0.125f; v.y *= 0.125f; v.z *= 0.125f; v.w *= 0.125f;
        *(float4*)(sQ + r*68 + c) = v;
    }
    if (tid < 64) { sMx[tid] = -1e30f; sL[tid] = 0.f; }

    float acc[4][4] = {};

    for (int kt = 0; kt <= qi; kt++) {
        __syncthreads();
        int k0 = kt * 64;
#pragma unroll
        for (int it = 0; it < 4; it++) {
            int idx = it*256 + tid;
            int r = idx >> 4, c = (idx & 15) << 2;
            *(float4*)(sK + r*68 + c) = *(const float4*)(Kg + (size_t)(k0 + r)*DD + c);
            *(float4*)(sV + r*68 + c) = *(const float4*)(Vg + (size_t)(k0 + r)*DD + c);
        }
        __syncthreads();

        float s[4][4] = {};
#pragma unroll
        for (int d4 = 0; d4 < 64; d4 += 4) {
            float4 qv[4], kv[4];
#pragma unroll
            for (int i = 0; i < 4; i++) qv[i] = *(float4*)(sQ + (ty+16*i)*68 + d4);
#pragma unroll
            for (int j = 0; j < 4; j++) kv[j] = *(float4*)(sK + (tx+16*j)*68 + d4);
#pragma unroll
            for (int i = 0; i < 4; i++)
#pragma unroll
                for (int j = 0; j < 4; j++)
                    s[i][j] += qv[i].x*kv[j].x + qv[i].y*kv[j].y
                             + qv[i].z*kv[j].z + qv[i].w*kv[j].w;
        }
        bool diag = (kt == qi);
#pragma unroll
        for (int i = 0; i < 4; i++) {
            int q = ty + 16*i;
#pragma unroll
            for (int j = 0; j < 4; j++) {
                int c = tx + 16*j;
                float v = s[i][j];
                if (diag && c > q) v = -1e30f;
                sS[q*68 + c] = v;
            }
        }
        __syncthreads();

        if (tid < 64) {
            int q = tid;
            float mo = sMx[q];
            float mn = mo;
            for (int c = 0; c < 64; c++) mn = fmaxf(mn, sS[q*68 + c]);
            float corr = __expf(mo - mn);
            float l = sL[q] * corr;
            for (int c = 0; c < 64; c++) {
                float p = __expf(sS[q*68 + c] - mn);
                sS[q*68 + c] = p;
                l += p;
            }
            sMx[q] = mn; sL[q] = l; sC[q] = corr;
        }
        __syncthreads();

#pragma unroll
        for (int i = 0; i < 4; i++) {
            float c_ = sC[ty + 16*i];
#pragma unroll
            for (int j = 0; j < 4; j++) acc[i][j] *= c_;
        }
#pragma unroll
        for (int k4 = 0; k4 < 64; k4 += 4) {
            float4 p[4], vv[4];
#pragma unroll
            for (int i = 0; i < 4; i++) p[i] = *(float4*)(sS + (ty+16*i)*68 + k4);
#pragma unroll
            for (int kk = 0; kk < 4; kk++) vv[kk] = *(float4*)(sV + (k4+kk)*68 + 4*tx);
#pragma unroll
            for (int i = 0; i < 4; i++) {
                acc[i][0] += p[i].x*vv[0].x + p[i].y*vv[1].x + p[i].z*vv[2].x + p[i].w*vv[3].x;
                acc[i][1] += p[i].x*vv[0].y + p[i].y*vv[1].y + p[i].z*vv[2].y + p[i].w*vv[3].y;
                acc[i][2] += p[i].x*vv[0].z + p[i].y*vv[1].z + p[i].z*vv[2].z + p[i].w*vv[3].z;
                acc[i][3] += p[i].x*vv[0].w + p[i].y*vv[1].w + p[i].z*vv[2].w + p[i].w*vv[3].w;
            }
        }
    }

    int b = bh >> 4, h = bh & 15;
#pragma unroll
    for (int i = 0; i < 4; i++) {
        int q = ty + 16*i;
        float inv = 1.0f / sL[q];
        float r0 = acc[i][0]*inv, r1 = acc[i][1]*inv, r2 = acc[i][2]*inv, r3 = acc[i][3]*inv;
        bf16 h0 = __float2bfloat16(r0), h1 = __float2bfloat16(r1);
        bf16 h2 = __float2bfloat16(r2), h3 = __float2bfloat16(r3);
        bf16 l0 = __float2bfloat16(r0 - __bfloat162float(h0));
        bf16 l1 = __float2bfloat16(r1 - __bfloat162float(h1));
        bf16 l2 = __float2bfloat16(r2 - __bfloat162float(h2));
        bf16 l3 = __float2bfloat16(r3 - __bfloat162float(h3));
        size_t off = ((size_t)(b*TT + q0 + q))*CC + h*DD + 4*tx;
        *(__nv_bfloat162*)(g_ah + off)     = __nv_bfloat162(h0, h1);
        *(__nv_bfloat162*)(g_ah + off + 2) = __nv_bfloat162(h2, h3);
        *(__nv_bfloat162*)(g_al + off)     = __nv_bfloat162(l0, l1);
        *(__nv_bfloat162*)(g_al + off + 2) = __nv_bfloat162(l2, l3);
    }
}

// ---------------------------------------------------------------------------
extern "C" void kernel_launch(void* const* d_in, const int* in_sizes, int n_in,
                              void* d_out, int out_size)
{
    (void)in_sizes; (void)n_in; (void)out_size;
    const float* x  = (const float*)d_in[0];
    const float* Wq = (const float*)d_in[1];
    const float* bq = (const float*)d_in[2];
    const float* Wk = (const float*)d_in[3];
    const float* bk = (const float*)d_in[4];
    const float* Wv = (const float*)d_in[5];
    const float* bv = (const float*)d_in[6];
    const float* Wo = (const float*)d_in[7];
    const float* bo = (const float*)d_in[8];
    float* out = (float*)d_out;

    float *q, *k, *v;
    bf16 *xh, *xl, *ah, *al, *wh, *wl;
    cudaGetSymbolAddress((void**)&q,  g_q);
    cudaGetSymbolAddress((void**)&k,  g_k);
    cudaGetSymbolAddress((void**)&v,  g_v);
    cudaGetSymbolAddress((void**)&xh, g_xh);
    cudaGetSymbolAddress((void**)&xl, g_xl);
    cudaGetSymbolAddress((void**)&ah, g_ah);
    cudaGetSymbolAddress((void**)&al, g_al);
    cudaGetSymbolAddress((void**)&wh, g_wh);
    cudaGetSymbolAddress((void**)&wl, g_wl);

    // 1. split x
    split_kernel<<<(MM*CC/4)/256, 256>>>(x, xh, xl);

    // 2. transpose+split weights
    dim3 tgrid(CC/32, CC/32), tblk(32, 8);
    tsplit_kernel<<<tgrid, tblk>>>(Wq, wh + 0*CC*CC, wl + 0*CC*CC);
    tsplit_kernel<<<tgrid, tblk>>>(Wk, wh + 1*CC*CC, wl + 1*CC*CC);
    tsplit_kernel<<<tgrid, tblk>>>(Wv, wh + 2*CC*CC, wl + 2*CC*CC);
    tsplit_kernel<<<tgrid, tblk>>>(Wo, wh + 3*CC*CC, wl + 3*CC*CC);

    // 3. QKV projections (mma.sync bf16x3)
    const int gsm = 2 * 65536;    // 128 KB
    cudaFuncSetAttribute(gemm_bf16x3<0>, cudaFuncAttributeMaxDynamicSharedMemorySize, gsm);
    cudaFuncSetAttribute(gemm_bf16x3<1>, cudaFuncAttributeMaxDynamicSharedMemorySize, gsm);
    dim3 ggrid(CC/128, MM/128);   // (8, 32)
    gemm_bf16x3<0><<<ggrid, 256, gsm>>>(xh, xl, wh + 0*CC*CC, wl + 0*CC*CC, bq, q);
    gemm_bf16x3<0><<<ggrid, 256, gsm>>>(xh, xl, wh + 1*CC*CC, wl + 1*CC*CC, bk, k);
    gemm_bf16x3<0><<<ggrid, 256, gsm>>>(xh, xl, wh + 2*CC*CC, wl + 2*CC*CC, bv, v);

    // 4. attention (fp32)
    const int attn_smem = (4*64*68 + 3*64) * (int)sizeof(float);
    cudaFuncSetAttribute(attn_kernel,
                         cudaFuncAttributeMaxDynamicSharedMemorySize, attn_smem);
    attn_kernel<<<dim3(TT/64, BB*HH), 256, attn_smem>>>();

    // 5. output projection -> d_out
    gemm_bf16x3<1><<<ggrid, 256, gsm>>>(ah, al, wh + 3*CC*CC, wl + 3*CC*CC, bo, out);
}

// round 4
// speedup vs baseline: 3.7385x; 1.8461x over previous
#include <cuda_runtime.h>
#include <cuda_bf16.h>
#include <cstdint>

// B=2, T=2048, C=1024, H=16, D=64, causal MHA, fp32 in/out.
#define BB 2
#define TT 2048
#define CC 1024
#define HH 16
#define DD 64
#define MM (BB*TT)

typedef __nv_bfloat16 bf16;

// ---------------- scratch (allocation-free) ----------------
__device__ bf16 g_xh[MM*CC], g_xl[MM*CC];        // split of x
__device__ bf16 g_ah[MM*CC], g_al[MM*CC];        // split of attended
__device__ bf16 g_wh[4*CC*CC], g_wl[4*CC*CC];    // transposed weight splits [n][k]
__device__ bf16 g_qh[BB*HH*TT*DD], g_ql[BB*HH*TT*DD];   // Q split (pre-scaled)
__device__ bf16 g_kh[BB*HH*TT*DD], g_kl[BB*HH*TT*DD];
__device__ bf16 g_vh[BB*HH*TT*DD], g_vl[BB*HH*TT*DD];

// ---------------- helpers (sm_80-baseline PTX only) ----------------
__device__ __forceinline__ uint32_t smem_u32(const void* p) {
    return (uint32_t)__cvta_generic_to_shared(p);
}

#define CP16(dst, src) \
    asm volatile("cp.async.cg.shared.global [%0], [%1], 16;" :: "r"(dst), "l"(src) : "memory")
#define CP_COMMIT() asm volatile("cp.async.commit_group;" ::: "memory")
#define CP_WAIT(n)  asm volatile("cp.async.wait_group %0;" :: "n"(n) : "memory")

__device__ __forceinline__ void ldm4(uint32_t* r, uint32_t a) {
    asm volatile("ldmatrix.sync.aligned.m8n8.x4.shared.b16 {%0,%1,%2,%3}, [%4];"
                 : "=r"(r[0]), "=r"(r[1]), "=r"(r[2]), "=r"(r[3]) : "r"(a));
}
__device__ __forceinline__ void ldm4t(uint32_t* r, uint32_t a) {
    asm volatile("ldmatrix.sync.aligned.m8n8.x4.trans.shared.b16 {%0,%1,%2,%3}, [%4];"
                 : "=r"(r[0]), "=r"(r[1]), "=r"(r[2]), "=r"(r[3]) : "r"(a));
}
__device__ __forceinline__ void mma_bf16(float* d, const uint32_t* a, const uint32_t* b) {
    asm volatile("mma.sync.aligned.m16n8k16.row.col.f32.bf16.bf16.f32 "
                 "{%0,%1,%2,%3}, {%4,%5,%6,%7}, {%8,%9}, {%0,%1,%2,%3};"
                 : "+f"(d[0]), "+f"(d[1]), "+f"(d[2]), "+f"(d[3])
                 : "r"(a[0]), "r"(a[1]), "r"(a[2]), "r"(a[3]), "r"(b[0]), "r"(b[1]));
}

__device__ __forceinline__ uint32_t pk2(float a, float b) {
    __nv_bfloat162 t;
    t.x = __float2bfloat16(a); t.y = __float2bfloat16(b);
    return *reinterpret_cast<uint32_t*>(&t);
}
__device__ __forceinline__ void split_st(bf16* hi, bf16* lo, size_t off, float a, float b) {
    bf16 h0 = __float2bfloat16(a), h1 = __float2bfloat16(b);
    *(__nv_bfloat162*)(hi + off) = __nv_bfloat162(h0, h1);
    *(__nv_bfloat162*)(lo + off) =
        __nv_bfloat162(__float2bfloat16(a - __bfloat162float(h0)),
                       __float2bfloat16(b - __bfloat162float(h1)));
}

// ---------------------------------------------------------------------------
// split x -> (hi, lo) bf16
// ---------------------------------------------------------------------------
__global__ void split_kernel(const float* __restrict__ x,
                             bf16* __restrict__ hi, bf16* __restrict__ lo) {
    int i = blockIdx.x * blockDim.x + threadIdx.x;
    float4 v = ((const float4*)x)[i];
    bf16 h0 = __float2bfloat16(v.x), h1 = __float2bfloat16(v.y);
    bf16 h2 = __float2bfloat16(v.z), h3 = __float2bfloat16(v.w);
    bf16 l0 = __float2bfloat16(v.x - __bfloat162float(h0));
    bf16 l1 = __float2bfloat16(v.y - __bfloat162float(h1));
    bf16 l2 = __float2bfloat16(v.z - __bfloat162float(h2));
    bf16 l3 = __float2bfloat16(v.w - __bfloat162float(h3));
    __nv_bfloat162* hp = (__nv_bfloat162*)(hi + 4*(size_t)i);
    __nv_bfloat162* lp = (__nv_bfloat162*)(lo + 4*(size_t)i);
    hp[0] = __nv_bfloat162(h0, h1); hp[1] = __nv_bfloat162(h2, h3);
    lp[0] = __nv_bfloat162(l0, l1); lp[1] = __nv_bfloat162(l2, l3);
}

// ---------------------------------------------------------------------------
// transpose + split: W[k][n] fp32 -> Wt_hi/lo[n][k] bf16
// ---------------------------------------------------------------------------
__global__ void tsplit_kernel(const float* __restrict__ W,
                              bf16* __restrict__ hi, bf16* __restrict__ lo) {
    __shared__ float t[32][33];
    int tx = threadIdx.x, ty = threadIdx.y;          // (32, 8)
    int n0 = blockIdx.x * 32, k0 = blockIdx.y * 32;
#pragma unroll
    for (int i = 0; i < 4; i++)
        t[ty + 8*i][tx] = W[(size_t)(k0 + ty + 8*i) * CC + n0 + tx];
    __syncthreads();
#pragma unroll
    for (int i = 0; i < 4; i++) {
        float v = t[tx][ty + 8*i];
        bf16 h = __float2bfloat16(v);
        bf16 l = __float2bfloat16(v - __bfloat162float(h));
        size_t o = (size_t)(n0 + ty + 8*i) * CC + k0 + tx;
        hi[o] = h; lo[o] = l;
    }
}

// ---------------------------------------------------------------------------
// mma.sync bf16x3 GEMM: 128x128x64 tiles, cp.async 2-stage, 8 warps (64x32).
// MODE 0: split-bf16 output remapped to [B,H,T,D], scaled.
// MODE 1: plain fp32 [M,N].
// ---------------------------------------------------------------------------
template<int MODE>
__global__ __launch_bounds__(256) void gemm_bf16x3(
    const bf16* __restrict__ Ah, const bf16* __restrict__ Al,
    const bf16* __restrict__ Bh, const bf16* __restrict__ Bl,
    const float* __restrict__ bias,
    float* __restrict__ outF, bf16* __restrict__ outH, bf16* __restrict__ outL,
    float scale)
{
    extern __shared__ char smraw[];
    const uint32_t sbase = smem_u32(smraw);

    int tid = threadIdx.x, lane = tid & 31, wid = tid >> 5;
    int wm = wid & 1, wn = wid >> 1;
    int m0 = blockIdx.y << 7, n0 = blockIdx.x << 7;

    float acc[4][4][4] = {};

    int arow = wm*64 + (lane & 15);
    int ahalf = lane >> 4;
    int brow = wn*32 + ((lane >> 4) << 3) + (lane & 7);
    int bhalf = (lane >> 3) & 1;

    auto load_stage = [&](int kt, int s) {
        uint32_t sb = sbase + s * 65536;
#pragma unroll
        for (int i = 0; i < 4; i++) {
            int id = tid + i*256;
            int r = id >> 3, c = id & 7;
            uint32_t phys = (uint32_t)(r*128 + ((c ^ (r & 7)) << 4));
            size_t ga = (size_t)(m0 + r)*CC + kt*64 + c*8;
            size_t gb = (size_t)(n0 + r)*CC + kt*64 + c*8;
            CP16(sb +         phys, Ah + ga);
            CP16(sb + 16384 + phys, Al + ga);
            CP16(sb + 32768 + phys, Bh + gb);
            CP16(sb + 49152 + phys, Bl + gb);
        }
        CP_COMMIT();
    };

    load_stage(0, 0);

    for (int kt = 0; kt < 16; kt++) {
        if (kt + 1 < 16) { load_stage(kt + 1, (kt + 1) & 1); CP_WAIT(1); }
        else             { CP_WAIT(0); }
        __syncthreads();

        uint32_t sb = sbase + (kt & 1) * 65536;
#pragma unroll
        for (int kk = 0; kk < 4; kk++) {
            uint32_t aswz = (uint32_t)(((kk*2 + ahalf) ^ (arow & 7)) << 4);
            uint32_t bswz = (uint32_t)(((kk*2 + bhalf) ^ (brow & 7)) << 4);
            uint32_t ahr[4][4], alr[4][4], bhr[2][4], blr[2][4];
#pragma unroll
            for (int mf = 0; mf < 4; mf++) {
                uint32_t off = (uint32_t)((arow + mf*16) * 128) + aswz;
                ldm4(ahr[mf], sb + off);
                ldm4(alr[mf], sb + 16384 + off);
            }
#pragma unroll
            for (int nh = 0; nh < 2; nh++) {
                uint32_t off = (uint32_t)((brow + nh*16) * 128) + bswz;
                ldm4(bhr[nh], sb + 32768 + off);
                ldm4(blr[nh], sb + 49152 + off);
            }
#pragma unroll
            for (int mf = 0; mf < 4; mf++)
#pragma unroll
                for (int nf = 0; nf < 4; nf++) {
                    const uint32_t* ph = bhr[nf >> 1] + (nf & 1)*2;
                    const uint32_t* pl = blr[nf >> 1] + (nf & 1)*2;
                    mma_bf16(acc[mf][nf], ahr[mf], ph);
                    mma_bf16(acc[mf][nf], ahr[mf], pl);
                    mma_bf16(acc[mf][nf], alr[mf], ph);
                }
        }
        __syncthreads();
    }

    int g = lane >> 2, t2 = (lane & 3) * 2;
#pragma unroll
    for (int nf = 0; nf < 4; nf++) {
        int col = n0 + wn*32 + nf*8 + t2;
        float2 bb = *(const float2*)(bias + col);
#pragma unroll
        for (int mf = 0; mf < 4; mf++) {
            int m1 = m0 + wm*64 + mf*16 + g;
            float v0 = acc[mf][nf][0] + bb.x, v1 = acc[mf][nf][1] + bb.y;
            float v2 = acc[mf][nf][2] + bb.x, v3 = acc[mf][nf][3] + bb.y;
            if (MODE == 0) {
                int h = col >> 6, d = col & 63;
                int b1 = m1 >> 11, t1 = m1 & (TT - 1);
                size_t base = ((size_t)(b1*HH + h)*TT) * DD + d;
                split_st(outH, outL, base + (size_t)t1*DD,       v0*scale, v1*scale);
                split_st(outH, outL, base + (size_t)(t1 + 8)*DD, v2*scale, v3*scale);
            } else {
                *(float2*)(outF + (size_t)m1*CC + col)       = make_float2(v0, v1);
                *(float2*)(outF + (size_t)(m1 + 8)*CC + col) = make_float2(v2, v3);
            }
        }
    }
}

// ---------------------------------------------------------------------------
// Tensor-core causal flash attention (bf16x3, fp32 accum).
// Block: 128 q-rows, 8 warps (16 rows each). k-tiles of 64, cp.async 2-stage.
// smem: Qh(16K) Ql(16K) | 2 stages x [Kh Kl Vh Vl](8K each) = 96KB.
// ---------------------------------------------------------------------------
__global__ __launch_bounds__(256) void attn_mma()
{
    extern __shared__ char smraw[];
    const uint32_t sb = smem_u32(smraw);
    const uint32_t QH = 0, QL = 16384, ST = 32768, STSZ = 32768;

    int tid = threadIdx.x, lane = tid & 31, w = tid >> 5;
    int bh = blockIdx.y;
    int qt = (int)gridDim.x - 1 - (int)blockIdx.x;   // heavy tiles first
    int q0 = qt * 128;
    int nkt = 2*qt + 2;

    const bf16* Qh = g_qh + (size_t)bh*TT*DD;
    const bf16* Ql = g_ql + (size_t)bh*TT*DD;
    const bf16* Kh = g_kh + (size_t)bh*TT*DD;
    const bf16* Kl = g_kl + (size_t)bh*TT*DD;
    const bf16* Vh = g_vh + (size_t)bh*TT*DD;
    const bf16* Vl = g_vl + (size_t)bh*TT*DD;

    // stage loader: 4 matrices x 64 rows x 8 16B-chunks
    auto load_kv = [&](int kt, int s) {
        uint32_t base = sb + ST + (uint32_t)s * STSZ;
        int k0 = kt * 64;
#pragma unroll
        for (int i = 0; i < 2; i++) {
            int id = tid + i*256;
            int r = id >> 3, c = id & 7;
            uint32_t phys = (uint32_t)(r*128 + ((c ^ (r & 7)) << 4));
            size_t gsrc = (size_t)(k0 + r)*DD + c*8;
            CP16(base +         phys, Kh + gsrc);
            CP16(base +  8192 + phys, Kl + gsrc);
            CP16(base + 16384 + phys, Vh + gsrc);
            CP16(base + 24576 + phys, Vl + gsrc);
        }
        CP_COMMIT();
    };

    // Q tile (128 x 64) hi/lo
#pragma unroll
    for (int m = 0; m < 2; m++)
#pragma unroll
        for (int i = 0; i < 4; i++) {
            int id = tid + i*256;
            int r = id >> 3, c = id & 7;
            uint32_t dst = sb + (m ? QL : QH) + (uint32_t)(r*128 + ((c ^ (r & 7)) << 4));
            const bf16* src = (m ? Ql : Qh) + (size_t)(q0 + r)*DD + c*8;
            CP16(dst, src);
        }
    CP_COMMIT();
    load_kv(0, 0);

    CP_WAIT(1);               // Q ready (kv0 may still be in flight)
    __syncthreads();

    // Q fragments
    uint32_t qfh[4][4], qfl[4][4];
    int arow = w*16 + (lane & 15), ahalf = lane >> 4;
#pragma unroll
    for (int kk = 0; kk < 4; kk++) {
        uint32_t off = (uint32_t)(arow*128 + (((2*kk + ahalf) ^ (arow & 7)) << 4));
        ldm4(qfh[kk], sb + QH + off);
        ldm4(qfl[kk], sb + QL + off);
    }

    float oacc[8][4] = {};
    float mrow0 = -1e30f, mrow1 = -1e30f;
    float lsum0 = 0.f, lsum1 = 0.f;

    int g = lane >> 2, t2 = (lane & 3) * 2;
    int r0g = q0 + 16*w + g, r1g = r0g + 8;
    int bhalf = (lane >> 3) & 1;
    int vi = lane >> 3, vr = lane & 7;

    for (int kt = 0; kt < nkt; kt++) {
        if (kt + 1 < nkt) { load_kv(kt + 1, (kt + 1) & 1); CP_WAIT(1); }
        else              { CP_WAIT(0); }
        __syncthreads();

        int k0 = kt * 64;
        if (k0 <= q0 + 16*w + 15) {   // skip fully-masked warps on diagonal tiles
            uint32_t st = sb + ST + (uint32_t)(kt & 1) * STSZ;

            // ---- S = Q K^T (3-product) ----
            float sacc[8][4] = {};
#pragma unroll
            for (int kk = 0; kk < 4; kk++) {
#pragma unroll
                for (int ng = 0; ng < 4; ng++) {
                    int brow = ng*16 + ((lane >> 4) << 3) + (lane & 7);
                    uint32_t off = (uint32_t)(brow*128 + (((2*kk + bhalf) ^ (brow & 7)) << 4));
                    uint32_t kh4[4], kl4[4];
                    ldm4(kh4, st + off);
                    ldm4(kl4, st + 8192 + off);
                    mma_bf16(sacc[2*ng],   qfh[kk], kh4);
                    mma_bf16(sacc[2*ng],   qfh[kk], kl4);
                    mma_bf16(sacc[2*ng],   qfl[kk], kh4);
                    mma_bf16(sacc[2*ng+1], qfh[kk], kh4 + 2);
                    mma_bf16(sacc[2*ng+1], qfh[kk], kl4 + 2);
                    mma_bf16(sacc[2*ng+1], qfl[kk], kh4 + 2);
                }
            }

            // ---- causal mask ----
            if (k0 + 63 > r0g) {
#pragma unroll
                for (int j = 0; j < 8; j++) {
                    int col = k0 + 8*j + t2;
                    if (col     > r0g) sacc[j][0] = -1e30f;
                    if (col + 1 > r0g) sacc[j][1] = -1e30f;
                    if (col     > r1g) sacc[j][2] = -1e30f;
                    if (col + 1 > r1g) sacc[j][3] = -1e30f;
                }
            }

            // ---- online softmax (FA2) ----
            float tm0 = -1e30f, tm1 = -1e30f;
#pragma unroll
            for (int j = 0; j < 8; j++) {
                tm0 = fmaxf(tm0, fmaxf(sacc[j][0], sacc[j][1]));
                tm1 = fmaxf(tm1, fmaxf(sacc[j][2], sacc[j][3]));
            }
            tm0 = fmaxf(tm0, __shfl_xor_sync(0xffffffffu, tm0, 1));
            tm0 = fmaxf(tm0, __shfl_xor_sync(0xffffffffu, tm0, 2));
            tm1 = fmaxf(tm1, __shfl_xor_sync(0xffffffffu, tm1, 1));
            tm1 = fmaxf(tm1, __shfl_xor_sync(0xffffffffu, tm1, 2));
            float mn0 = fmaxf(mrow0, tm0), mn1 = fmaxf(mrow1, tm1);
            float c0 = __expf(mrow0 - mn0), c1 = __expf(mrow1 - mn1);
            mrow0 = mn0; mrow1 = mn1;

            float ps0 = 0.f, ps1 = 0.f;
            uint32_t pfh[4][4], pfl[4][4];
#pragma unroll
            for (int kc = 0; kc < 4; kc++) {
#pragma unroll
                for (int jj = 0; jj < 2; jj++) {
                    int j = 2*kc + jj;
                    float p0 = __expf(sacc[j][0] - mn0);
                    float p1 = __expf(sacc[j][1] - mn0);
                    float p2 = __expf(sacc[j][2] - mn1);
                    float p3 = __expf(sacc[j][3] - mn1);
                    ps0 += p0 + p1; ps1 += p2 + p3;
                    float h0 = __bfloat162float(__float2bfloat16(p0));
                    float h1 = __bfloat162float(__float2bfloat16(p1));
                    float h2 = __bfloat162float(__float2bfloat16(p2));
                    float h3 = __bfloat162float(__float2bfloat16(p3));
                    pfh[kc][2*jj]   = pk2(h0, h1);
                    pfh[kc][2*jj+1] = pk2(h2, h3);
                    pfl[kc][2*jj]   = pk2(p0 - h0, p1 - h1);
                    pfl[kc][2*jj+1] = pk2(p2 - h2, p3 - h3);
                }
            }
            lsum0 = lsum0 * c0 + ps0;
            lsum1 = lsum1 * c1 + ps1;
#pragma unroll
            for (int j = 0; j < 8; j++) {
                oacc[j][0] *= c0; oacc[j][1] *= c0;
                oacc[j][2] *= c1; oacc[j][3] *= c1;
            }

            // ---- O += P V (3-product), V frags via ldmatrix.trans ----
#pragma unroll
            for (int kc = 0; kc < 4; kc++) {
#pragma unroll
                for (int dg = 0; dg < 4; dg++) {
                    int key = kc*16 + 8*(vi & 1) + vr;
                    int dc = 2*dg + (vi >> 1);
                    uint32_t off = (uint32_t)(key*128 + ((dc ^ (key & 7)) << 4));
                    uint32_t vh4[4], vl4[4];
                    ldm4t(vh4, st + 16384 + off);
                    ldm4t(vl4, st + 24576 + off);
                    mma_bf16(oacc[2*dg],   pfh[kc], vh4);
                    mma_bf16(oacc[2*dg],   pfh[kc], vl4);
                    mma_bf16(oacc[2*dg],   pfl[kc], vh4);
                    mma_bf16(oacc[2*dg+1], pfh[kc], vh4 + 2);
                    mma_bf16(oacc[2*dg+1], pfh[kc], vl4 + 2);
                    mma_bf16(oacc[2*dg+1], pfl[kc], vh4 + 2);
                }
            }
        }
        __syncthreads();
    }

    // ---- finalize: row sums, normalize, write split bf16 attended [B,T,C] ----
    lsum0 += __shfl_xor_sync(0xffffffffu, lsum0, 1);
    lsum0 += __shfl_xor_sync(0xffffffffu, lsum0, 2);
    lsum1 += __shfl_xor_sync(0xffffffffu, lsum1, 1);
    lsum1 += __shfl_xor_sync(0xffffffffu, lsum1, 2);
    float inv0 = 1.f / lsum0, inv1 = 1.f / lsum1;

    int b = bh >> 4, h = bh & 15;
    size_t row0 = (size_t)(b*TT + r0g) * CC + h*DD;
    size_t row1 = (size_t)(b*TT + r1g) * CC + h*DD;
#pragma unroll
    for (int j = 0; j < 8; j++) {
        int d = 8*j + t2;
        split_st(g_ah, g_al, row0 + d, oacc[j][0]*inv0, oacc[j][1]*inv0);
        split_st(g_ah, g_al, row1 + d, oacc[j][2]*inv1, oacc[j][3]*inv1);
    }
}

// ---------------------------------------------------------------------------
extern "C" void kernel_launch(void* const* d_in, const int* in_sizes, int n_in,
                              void* d_out, int out_size)
{
    (void)in_sizes; (void)n_in; (void)out_size;
    const float* x  = (const float*)d_in[0];
    const float* Wq = (const float*)d_in[1];
    const float* bq = (const float*)d_in[2];
    const float* Wk = (const float*)d_in[3];
    const float* bk = (const float*)d_in[4];
    const float* Wv = (const float*)d_in[5];
    const float* bv = (const float*)d_in[6];
    const float* Wo = (const float*)d_in[7];
    const float* bo = (const float*)d_in[8];
    float* out = (float*)d_out;

    bf16 *xh, *xl, *ah, *al, *wh, *wl, *qh, *ql, *kh, *kl, *vh, *vl;
    cudaGetSymbolAddress((void**)&xh, g_xh);
    cudaGetSymbolAddress((void**)&xl, g_xl);
    cudaGetSymbolAddress((void**)&ah, g_ah);
    cudaGetSymbolAddress((void**)&al, g_al);
    cudaGetSymbolAddress((void**)&wh, g_wh);
    cudaGetSymbolAddress((void**)&wl, g_wl);
    cudaGetSymbolAddress((void**)&qh, g_qh);
    cudaGetSymbolAddress((void**)&ql, g_ql);
    cudaGetSymbolAddress((void**)&kh, g_kh);
    cudaGetSymbolAddress((void**)&kl, g_kl);
    cudaGetSymbolAddress((void**)&vh, g_vh);
    cudaGetSymbolAddress((void**)&vl, g_vl);

    // 1. split x
    split_kernel<<<(MM*CC/4)/256, 256>>>(x, xh, xl);

    // 2. transpose+split weights
    dim3 tgrid(CC/32, CC/32), tblk(32, 8);
    tsplit_kernel<<<tgrid, tblk>>>(Wq, wh + 0*CC*CC, wl + 0*CC*CC);
    tsplit_kernel<<<tgrid, tblk>>>(Wk, wh + 1*CC*CC, wl + 1*CC*CC);
    tsplit_kernel<<<tgrid, tblk>>>(Wv, wh + 2*CC*CC, wl + 2*CC*CC);
    tsplit_kernel<<<tgrid, tblk>>>(Wo, wh + 3*CC*CC, wl + 3*CC*CC);

    // 3. QKV projections -> split bf16 [B,H,T,D] (Q pre-scaled by 1/8)
    const int gsm = 2 * 65536;
    cudaFuncSetAttribute(gemm_bf16x3<0>, cudaFuncAttributeMaxDynamicSharedMemorySize, gsm);
    cudaFuncSetAttribute(gemm_bf16x3<1>, cudaFuncAttributeMaxDynamicSharedMemorySize, gsm);
    dim3 ggrid(CC/128, MM/128);
    gemm_bf16x3<0><<<ggrid, 256, gsm>>>(xh, xl, wh + 0*CC*CC, wl + 0*CC*CC, bq,
                                        nullptr, qh, ql, 0.125f);
    gemm_bf16x3<0><<<ggrid, 256, gsm>>>(xh, xl, wh + 1*CC*CC, wl + 1*CC*CC, bk,
                                        nullptr, kh, kl, 1.0f);
    gemm_bf16x3<0><<<ggrid, 256, gsm>>>(xh, xl, wh + 2*CC*CC, wl + 2*CC*CC, bv,
                                        nullptr, vh, vl, 1.0f);

    // 4. tensor-core flash attention
    const int asm_sz = 98304;
    cudaFuncSetAttribute(attn_mma, cudaFuncAttributeMaxDynamicSharedMemorySize, asm_sz);
    attn_mma<<<dim3(TT/128, BB*HH), 256, asm_sz>>>();

    // 5. output projection -> d_out (fp32)
    gemm_bf16x3<1><<<ggrid, 256, gsm>>>(ah, al, wh + 3*CC*CC, wl + 3*CC*CC, bo,
                                        out, nullptr, nullptr, 1.0f);
}